// round 4
// baseline (speedup 1.0000x reference)
#include <cuda_runtime.h>

// Problem constants (fixed by the reference)
#define NB  32
#define NN  1024
#define NE  16384
#define NT  8
#define NDS 8
#define NH  32

// Scratch (no dynamic allocation allowed)
__device__ int   g_winner[NN * NN];    // 4 MB: per-cell winning priority, -1 = untouched
__device__ float g_score[NB * NE];     // 2 MB: per (batch, edge) score

// ---------------------------------------------------------------------------
// K1: clear the ENTIRE winner plane to -1 (int4-vectorized).
// Device globals start at 0, and graph replays leave stale marks, so a full
// clear every launch is required for determinism and correctness.
// ---------------------------------------------------------------------------
__global__ void k_clear() {
    unsigned idx = blockIdx.x * blockDim.x + threadIdx.x;       // int4 index
    const unsigned TOT4 = NN * NN / 4;                          // 262,144
    if (idx >= TOT4) return;
    reinterpret_cast<int4*>(g_winner)[idx] = make_int4(-1, -1, -1, -1);
}

// ---------------------------------------------------------------------------
// K2: priority scatter. pass1 (src,dst) priority=e, pass2 (dst,src) priority=E+e.
// atomicMax => within a pass the LAST edge wins; pass2 overrides pass1,
// matching the reference's sequential .at[].set() semantics.
// ---------------------------------------------------------------------------
__global__ void k_mark(const int* __restrict__ ei) {
    int t = blockIdx.x * blockDim.x + threadIdx.x;
    if (t >= 2 * NE) return;
    int e = (t < NE) ? t : t - NE;
    int s = ei[e];
    int d = ei[NE + e];
    int cell = (t < NE) ? (s * NN + d) : (d * NN + s);
    atomicMax(&g_winner[cell], t);
}

// ---------------------------------------------------------------------------
// K3: edge MLP scores.  One thread per (b, e).
// score = w2 . relu(w1^T [dist, rest, dist-rest, emb[type]] + b1) + b2
// ---------------------------------------------------------------------------
__global__ void k_score(const float* __restrict__ xyz,
                        const int*   __restrict__ ei,
                        const int*   __restrict__ etype,
                        const float* __restrict__ rest,
                        const float* __restrict__ temb,
                        const float* __restrict__ w1,
                        const float* __restrict__ b1,
                        const float* __restrict__ w2,
                        const float* __restrict__ b2) {
    __shared__ float s_w1[(3 + NDS) * NH];   // 352
    __shared__ float s_b1[NH];
    __shared__ float s_w2[NH];
    __shared__ float s_temb[NT * NDS];       // 64
    __shared__ float s_b2;

    int tid = threadIdx.x;
    for (int i = tid; i < (3 + NDS) * NH; i += blockDim.x) s_w1[i] = w1[i];
    if (tid < NH) { s_b1[tid] = b1[tid]; s_w2[tid] = w2[tid]; }
    for (int i = tid; i < NT * NDS; i += blockDim.x) s_temb[i] = temb[i];
    if (tid == 0) s_b2 = b2[0];
    __syncthreads();

    int t = blockIdx.x * blockDim.x + tid;
    if (t >= NB * NE) return;
    int e = t & (NE - 1);
    int b = t >> 14;                 // t / NE

    int s = ei[e];
    int d = ei[NE + e];
    const float* ps = xyz + ((long)b * NN + s) * 3;
    const float* pd = xyz + ((long)b * NN + d) * 3;
    float dx = pd[0] - ps[0];
    float dy = pd[1] - ps[1];
    float dz = pd[2] - ps[2];
    float dist = sqrtf(fmaf(dx, dx, fmaf(dy, dy, fmaf(dz, dz, 1e-12f))));
    float r   = rest[e];
    float dmr = dist - r;

    const float* emb = s_temb + etype[e] * NDS;
    float e0 = emb[0], e1 = emb[1], e2 = emb[2], e3 = emb[3];
    float e4 = emb[4], e5 = emb[5], e6 = emb[6], e7 = emb[7];

    float score = s_b2;
#pragma unroll
    for (int j = 0; j < NH; j++) {
        float h = s_b1[j];
        h = fmaf(dist, s_w1[0 * NH + j], h);
        h = fmaf(r,    s_w1[1 * NH + j], h);
        h = fmaf(dmr,  s_w1[2 * NH + j], h);
        h = fmaf(e0, s_w1[3 * NH + j], h);
        h = fmaf(e1, s_w1[4 * NH + j], h);
        h = fmaf(e2, s_w1[5 * NH + j], h);
        h = fmaf(e3, s_w1[6 * NH + j], h);
        h = fmaf(e4, s_w1[7 * NH + j], h);
        h = fmaf(e5, s_w1[8 * NH + j], h);
        h = fmaf(e6, s_w1[9 * NH + j], h);
        h = fmaf(e7, s_w1[10 * NH + j], h);
        h = fmaxf(h, 0.0f);
        score = fmaf(h, s_w2[j], score);
    }
    g_score[t] = score;              // layout [b][e] == t
}

// ---------------------------------------------------------------------------
// K4: fused fill + scatter. float4 stores over the 128 MiB output.
// Winner plane (4 MB) is batch-invariant -> L2-resident across the 32 reuses.
// ---------------------------------------------------------------------------
__global__ void k_fill(float* __restrict__ out, const float* __restrict__ dflt) {
    unsigned idx = blockIdx.x * blockDim.x + threadIdx.x;   // float4 index
    const unsigned TOT4 = (unsigned)NB * NN * NN / 4;       // 8,388,608
    if (idx >= TOT4) return;

    unsigned cell4 = idx & ((NN * NN / 4) - 1);             // 2^18 per plane
    unsigned b     = idx >> 18;

    float dv = __ldg(dflt);
    int4 w = reinterpret_cast<const int4*>(g_winner)[cell4];
    float4 v = make_float4(dv, dv, dv, dv);
    const float* sc = g_score + b * NE;

    if (w.x >= 0) v.x = sc[w.x < NE ? w.x : w.x - NE];
    if (w.y >= 0) v.y = sc[w.y < NE ? w.y : w.y - NE];
    if (w.z >= 0) v.z = sc[w.z < NE ? w.z : w.z - NE];
    if (w.w >= 0) v.w = sc[w.w < NE ? w.w : w.w - NE];

    reinterpret_cast<float4*>(out)[idx] = v;
}

// ---------------------------------------------------------------------------
// kernel_launch
// Input order (metadata.txt): xyz, edge_index, edge_type, edge_rest_lengths,
//                             type_emb, w1, b1, w2, b2, default_bias
// ---------------------------------------------------------------------------
extern "C" void kernel_launch(void* const* d_in, const int* in_sizes, int n_in,
                              void* d_out, int out_size) {
    const float* xyz   = (const float*)d_in[0];
    const int*   ei    = (const int*)  d_in[1];
    const int*   etype = (const int*)  d_in[2];
    const float* rest  = (const float*)d_in[3];
    const float* temb  = (const float*)d_in[4];
    const float* w1    = (const float*)d_in[5];
    const float* b1    = (const float*)d_in[6];
    const float* w2    = (const float*)d_in[7];
    const float* b2    = (const float*)d_in[8];
    const float* dflt  = (const float*)d_in[9];
    float* out = (float*)d_out;

    // K1: full winner-plane clear (int4 stores over 4 MB)
    {
        int threads = 256;
        unsigned tot4 = NN * NN / 4;
        int blocks = (int)((tot4 + threads - 1) / threads);  // 1024
        k_clear<<<blocks, threads>>>();
    }
    // K2: priority scatter (ordering via stream dependency)
    {
        int threads = 256;
        int blocks = (2 * NE + threads - 1) / threads;       // 128
        k_mark<<<blocks, threads>>>(ei);
    }
    // K3: scores
    {
        int threads = 256;
        int blocks = (NB * NE + threads - 1) / threads;      // 2048
        k_score<<<blocks, threads>>>(xyz, ei, etype, rest, temb, w1, b1, w2, b2);
    }
    // K4: fused fill + scatter
    {
        int threads = 256;
        unsigned tot4 = (unsigned)NB * NN * NN / 4;
        int blocks = (int)((tot4 + threads - 1) / threads);  // 32768
        k_fill<<<blocks, threads>>>(out, dflt);
    }
}